// round 3
// baseline (speedup 1.0000x reference)
#include <cuda_runtime.h>
#include <cuda_bf16.h>
#include <cstdint>

#define NTOK_MAX (8 * 4096)
#define IN_F 1024
#define CUT1 5000
#define CUT2 20000

__device__ int g_cnt[2];
__device__ int g_idx0[NTOK_MAX];
__device__ int g_idx1[NTOK_MAX];

// Dense packed split-bf16 operands.
// A' row layout: [Ah(K) | Al(K) | Ah(K)]   (K' = 3K)
// B' row layout: [Bh(K) | Bh(K) | Bl(K)]
__device__ __align__(16) __nv_bfloat16 g_A0[NTOK_MAX * 1536];  // tail0 gathered
__device__ __align__(16) __nv_bfloat16 g_A1[NTOK_MAX * 768];   // tail1 gathered
__device__ __align__(16) __nv_bfloat16 g_B0[1024 * 1536];
__device__ __align__(16) __nv_bfloat16 g_B1[1024 * 768];

// ---------------------------------------------------------------------------
__global__ void init_k() { g_cnt[0] = 0; g_cnt[1] = 0; }

__global__ void classify_k(const int* __restrict__ tokens, int n) {
    int i = blockIdx.x * blockDim.x + threadIdx.x;
    int t = (i < n) ? tokens[i] : -1;
    int c = (t >= CUT2) ? 1 : ((t >= CUT1) ? 0 : -1);
    int lane = threadIdx.x & 31;
#pragma unroll
    for (int cc = 0; cc < 2; ++cc) {
        unsigned m = __ballot_sync(0xffffffffu, c == cc);
        if (c == cc) {
            int leader = __ffs(m) - 1;
            int base = 0;
            if (lane == leader) base = atomicAdd(&g_cnt[cc], __popc(m));
            base = __shfl_sync(m, base, leader);
            int off = base + __popc(m & ((1u << lane) - 1u));
            if (cc == 0) g_idx0[off] = i;
            else         g_idx1[off] = i;
        }
    }
}

__global__ void head_copy_k(const int* __restrict__ tokens,
                            const float* __restrict__ head_emb,
                            float* __restrict__ out) {
    int p = blockIdx.x;
    int t = __ldg(&tokens[p]);
    if (t >= CUT1) return;
    const float4* src = (const float4*)(head_emb + (size_t)t * IN_F);
    float4* dst = (float4*)(out + (size_t)p * IN_F);
    dst[threadIdx.x]       = src[threadIdx.x];
    dst[threadIdx.x + 128] = src[threadIdx.x + 128];
}

// ---------------------------------------------------------------------------
__device__ __forceinline__ void hilo4(float4 v, uint2& hi, uint2& lo) {
    float f[4] = {v.x, v.y, v.z, v.w};
    __nv_bfloat16 h[4], l[4];
#pragma unroll
    for (int i = 0; i < 4; i++) {
        h[i] = __float2bfloat16(f[i]);
        l[i] = __float2bfloat16(f[i] - __bfloat162float(h[i]));
    }
    hi.x = ((uint32_t)*(uint16_t*)&h[1] << 16) | *(uint16_t*)&h[0];
    hi.y = ((uint32_t)*(uint16_t*)&h[3] << 16) | *(uint16_t*)&h[2];
    lo.x = ((uint32_t)*(uint16_t*)&l[1] << 16) | *(uint16_t*)&l[0];
    lo.y = ((uint32_t)*(uint16_t*)&l[3] << 16) | *(uint16_t*)&l[2];
}

// Gather + split-convert token embedding rows into dense A' (list order).
template <int K, int LOW, int C>
__global__ void pack_emb_k(const float* __restrict__ emb,
                           const int* __restrict__ tokens,
                           __nv_bfloat16* __restrict__ Ap) {
    constexpr int TPR = K / 4;            // threads per row
    constexpr int RPB = 256 / TPR;        // rows per block
    const int count = g_cnt[C];
    int r = blockIdx.x * RPB + threadIdx.x / TPR;
    if (r >= count) return;
    int j = (threadIdx.x % TPR) * 4;
    const int* idxList = (C == 0) ? g_idx0 : g_idx1;
    int tok = __ldg(&tokens[idxList[r]]);
    float4 v = *(const float4*)(emb + (size_t)(tok - LOW) * K + j);
    uint2 hi, lo;
    hilo4(v, hi, lo);
    __nv_bfloat16* row = Ap + (size_t)r * (3 * K);
    *(uint2*)(row + j)         = hi;
    *(uint2*)(row + K + j)     = lo;
    *(uint2*)(row + 2 * K + j) = hi;
}

// Split-convert weight rows into dense B'.
template <int K>
__global__ void pack_w_k(const float* __restrict__ w,
                         __nv_bfloat16* __restrict__ Bp) {
    constexpr int TPR = K / 4;
    constexpr int RPB = 256 / TPR;
    int r = blockIdx.x * RPB + threadIdx.x / TPR;  // r < 1024 by grid
    int j = (threadIdx.x % TPR) * 4;
    float4 v = *(const float4*)(w + (size_t)r * K + j);
    uint2 hi, lo;
    hilo4(v, hi, lo);
    __nv_bfloat16* row = Bp + (size_t)r * (3 * K);
    *(uint2*)(row + j)         = hi;
    *(uint2*)(row + K + j)     = hi;
    *(uint2*)(row + 2 * K + j) = lo;
}

// ---------------------------------------------------------------------------
__device__ __forceinline__ void ldsm_x4(uint32_t& r0, uint32_t& r1,
                                        uint32_t& r2, uint32_t& r3,
                                        const void* smem_ptr) {
    uint32_t addr = (uint32_t)__cvta_generic_to_shared(smem_ptr);
    asm volatile("ldmatrix.sync.aligned.m8n8.x4.shared.b16 {%0,%1,%2,%3}, [%4];"
                 : "=r"(r0), "=r"(r1), "=r"(r2), "=r"(r3) : "r"(addr));
}

__device__ __forceinline__ void mma16816(float* c, const uint32_t* a,
                                         uint32_t b0, uint32_t b1) {
    asm volatile(
        "mma.sync.aligned.m16n8k16.row.col.f32.bf16.bf16.f32 "
        "{%0,%1,%2,%3}, {%4,%5,%6,%7}, {%8,%9}, {%0,%1,%2,%3};"
        : "+f"(c[0]), "+f"(c[1]), "+f"(c[2]), "+f"(c[3])
        : "r"(a[0]), "r"(a[1]), "r"(a[2]), "r"(a[3]), "r"(b0), "r"(b1));
}

__device__ __forceinline__ void cp16(void* dst_smem, const void* src) {
    uint32_t d = (uint32_t)__cvta_generic_to_shared(dst_smem);
    asm volatile("cp.async.cg.shared.global [%0], [%1], 16;\n" :: "r"(d), "l"(src));
}

// ---------------------------------------------------------------------------
// Dense bf16 GEMM: out[pos[r], n] += sum_k A'[r,k] B'[n,k]
// Tile 128x128, TK=32, 3-stage cp.async pipeline, 8 warps (2M x 4N, 64x32 each).
template <int K3, int C>
__global__ void __launch_bounds__(256, 2)
tail_mma2_k(const __nv_bfloat16* __restrict__ Ap,
            const __nv_bfloat16* __restrict__ Bp,
            float* __restrict__ out) {
    constexpr int TM = 128, TN = 128, LD = 40;   // LD in halves (32 + 8 pad)
    constexpr int NC = K3 / 32;
    extern __shared__ __nv_bfloat16 smem[];
    __nv_bfloat16* As = smem;                    // [3][TM][LD]
    __nv_bfloat16* Bs = smem + 3 * TM * LD;      // [3][TN][LD]
    __shared__ int sPos[TM];

    const int count = g_cnt[C];
    const int rowBase = blockIdx.x * TM;
    if (rowBase >= count) return;
    const int rem = min(TM, count - rowBase);
    const int n0 = blockIdx.y * TN;
    const int tid = threadIdx.x;
    const int lane = tid & 31;
    const int wid = tid >> 5;
    const int* idxList = (C == 0) ? g_idx0 : g_idx1;

    if (tid < TM) sPos[tid] = idxList[rowBase + min(tid, rem - 1)];

    // loader lanes: 4 threads per row segment
    const int lr = tid >> 2;          // 0..63
    const int seg = (tid & 3) * 8;    // half offset of 16B segment
    const __nv_bfloat16* a0 = Ap + (size_t)(rowBase + min(lr, rem - 1)) * K3 + seg;
    const __nv_bfloat16* a1 = Ap + (size_t)(rowBase + min(lr + 64, rem - 1)) * K3 + seg;
    const __nv_bfloat16* b0 = Bp + (size_t)(n0 + lr) * K3 + seg;
    const __nv_bfloat16* b1 = Bp + (size_t)(n0 + lr + 64) * K3 + seg;

#define ISSUE(s, kc)                                                     \
    do {                                                                 \
        cp16(&As[((s) * TM + lr) * LD + seg], a0 + (kc) * 32);           \
        cp16(&As[((s) * TM + lr + 64) * LD + seg], a1 + (kc) * 32);      \
        cp16(&Bs[((s) * TN + lr) * LD + seg], b0 + (kc) * 32);           \
        cp16(&Bs[((s) * TN + lr + 64) * LD + seg], b1 + (kc) * 32);      \
    } while (0)

    ISSUE(0, 0);
    asm volatile("cp.async.commit_group;\n");
    ISSUE(1, 1);
    asm volatile("cp.async.commit_group;\n");

    const int wm = (wid & 1) * 64;
    const int wn = (wid >> 1) * 32;
    float c[4][4][4];
#pragma unroll
    for (int i = 0; i < 4; i++)
#pragma unroll
        for (int j = 0; j < 4; j++)
#pragma unroll
            for (int q = 0; q < 4; q++) c[i][j][q] = 0.f;

    const int aLdRow = lane & 15;
    const int aLdCol = (lane >> 4) * 8;
    const int bLdRow = ((lane >> 4) << 3) + (lane & 7);
    const int bLdCol = lane & 8;

    int s = 0;
    for (int kc = 0; kc < NC; kc++) {
        asm volatile("cp.async.wait_group 1;\n");
        __syncthreads();

        int kn = kc + 2;
        if (kn < NC) {
            int sn = (s + 2 >= 3) ? s - 1 : s + 2;
            ISSUE(sn, kn);
        }
        asm volatile("cp.async.commit_group;\n");

        const __nv_bfloat16* Ab = &As[s * TM * LD];
        const __nv_bfloat16* Bb = &Bs[s * TN * LD];
#pragma unroll
        for (int kf = 0; kf < 2; kf++) {
            uint32_t aF[4][4], bF[2][4];
#pragma unroll
            for (int mf = 0; mf < 4; mf++)
                ldsm_x4(aF[mf][0], aF[mf][1], aF[mf][2], aF[mf][3],
                        &Ab[(wm + mf * 16 + aLdRow) * LD + kf * 16 + aLdCol]);
#pragma unroll
            for (int g = 0; g < 2; g++)
                ldsm_x4(bF[g][0], bF[g][1], bF[g][2], bF[g][3],
                        &Bb[(wn + g * 16 + bLdRow) * LD + kf * 16 + bLdCol]);
#pragma unroll
            for (int mf = 0; mf < 4; mf++)
#pragma unroll
                for (int nf = 0; nf < 4; nf++)
                    mma16816(c[mf][nf], aF[mf],
                             bF[nf >> 1][(nf & 1) * 2], bF[nf >> 1][(nf & 1) * 2 + 1]);
        }
        s = (s == 2) ? 0 : s + 1;
    }
#undef ISSUE

    // scatter epilogue
#pragma unroll
    for (int mf = 0; mf < 4; mf++) {
#pragma unroll
        for (int nf = 0; nf < 4; nf++) {
            int r0 = wm + mf * 16 + (lane >> 2);
            int col = n0 + wn + nf * 8 + 2 * (lane & 3);
            if (r0 < rem)
                *(float2*)(out + (size_t)sPos[r0] * IN_F + col) =
                    make_float2(c[mf][nf][0], c[mf][nf][1]);
            if (r0 + 8 < rem)
                *(float2*)(out + (size_t)sPos[r0 + 8] * IN_F + col) =
                    make_float2(c[mf][nf][2], c[mf][nf][3]);
        }
    }
}

// ---------------------------------------------------------------------------
extern "C" void kernel_launch(void* const* d_in, const int* in_sizes, int n_in,
                              void* d_out, int out_size) {
    const int*   tokens   = (const int*)d_in[0];
    const float* head_emb = (const float*)d_in[1];
    const float* t0e      = (const float*)d_in[2];
    const float* t0w      = (const float*)d_in[3];
    const float* t1e      = (const float*)d_in[4];
    const float* t1w      = (const float*)d_in[5];
    float* out = (float*)d_out;
    int n = in_sizes[0];
    if (n > NTOK_MAX) n = NTOK_MAX;

    init_k<<<1, 1>>>();
    classify_k<<<(n + 255) / 256, 256>>>(tokens, n);
    head_copy_k<<<n, 128>>>(tokens, head_emb, out);

    // pack passes
    pack_emb_k<512, CUT1, 0><<<(n + 1) / 2, 256>>>(t0e, tokens, g_A0);
    pack_emb_k<256, CUT2, 1><<<(n + 3) / 4, 256>>>(t1e, tokens, g_A1);
    pack_w_k<512><<<1024 / 2, 256>>>(t0w, g_B0);
    pack_w_k<256><<<1024 / 4, 256>>>(t1w, g_B1);

    // dense GEMMs
    const int smemBytes = 3 * (128 + 128) * 40 * (int)sizeof(__nv_bfloat16);  // 61440
    static bool attrDone = false;
    if (!attrDone) {
        cudaFuncSetAttribute(tail_mma2_k<1536, 0>,
                             cudaFuncAttributeMaxDynamicSharedMemorySize, smemBytes);
        cudaFuncSetAttribute(tail_mma2_k<768, 1>,
                             cudaFuncAttributeMaxDynamicSharedMemorySize, smemBytes);
        attrDone = true;
    }
    dim3 grid((n + 127) / 128, IN_F / 128);
    tail_mma2_k<1536, 0><<<grid, 256, smemBytes>>>(g_A0, g_B0, out);
    tail_mma2_k<768, 1><<<grid, 256, smemBytes>>>(g_A1, g_B1, out);
}